// round 13
// baseline (speedup 1.0000x reference)
#include <cuda_runtime.h>
#include <cuda_fp16.h>
#include <cstdint>

// ============================================================================
// Problem dims
// ============================================================================
#define B_DIM 4
#define S_DIM 4096
#define D_DIM 1024
#define M_TOT (B_DIM * S_DIM)   // 16384

// ============================================================================
// Device scratch (allocation-free rule -> static __device__ arrays)
// ============================================================================
__device__ __align__(128) __half g_xh[M_TOT * D_DIM];     // 32 MB (x as fp16)
__device__ __align__(128) __half g_w[3][D_DIM * D_DIM];   // 6 MB  (Wg,Wv,Wd fp16)
// chained-scan carry: 64 chains x 16 positions x 64 channels
__device__ __align__(128) float        g_carry[64 * 16 * 64];
__device__ __align__(128) unsigned int g_flags[64 * 16];
__device__ int g_ticket;

// ============================================================================
// PTX helpers (sm_80-level features: mma.sync + cp.async + ldmatrix)
// ============================================================================
__device__ __forceinline__ uint32_t smem_to_u32(const void* p) {
    uint32_t a;
    asm("{ .reg .u64 t; cvta.to.shared.u64 t, %1; cvt.u32.u64 %0, t; }"
        : "=r"(a) : "l"(p));
    return a;
}

__device__ __forceinline__ void cp16(uint32_t dst, const void* src) {
    asm volatile("cp.async.cg.shared.global [%0], [%1], 16;"
                 :: "r"(dst), "l"(src) : "memory");
}
__device__ __forceinline__ void cp_commit() {
    asm volatile("cp.async.commit_group;" ::: "memory");
}

__device__ __forceinline__ void ldsm4(uint32_t* r, uint32_t addr) {
    asm volatile("ldmatrix.sync.aligned.m8n8.x4.shared.b16 {%0,%1,%2,%3}, [%4];"
                 : "=r"(r[0]), "=r"(r[1]), "=r"(r[2]), "=r"(r[3]) : "r"(addr));
}

// D += A * B  (m16n8k16, fp16 in, f32 accum, A row-major, B col-major)
__device__ __forceinline__ void mma16816(float* c, const uint32_t* a, const uint32_t* b) {
    asm volatile(
        "mma.sync.aligned.m16n8k16.row.col.f32.f16.f16.f32 "
        "{%0,%1,%2,%3}, {%4,%5,%6,%7}, {%8,%9}, {%0,%1,%2,%3};"
        : "+f"(c[0]), "+f"(c[1]), "+f"(c[2]), "+f"(c[3])
        : "r"(a[0]), "r"(a[1]), "r"(a[2]), "r"(a[3]), "r"(b[0]), "r"(b[1]));
}

// ============================================================================
// Kernel 1: fused fp32 -> fp16 conversion + per-launch sync-state reset
// ============================================================================
#define X_F4   (M_TOT * D_DIM / 4)          // 4194304 float4s
#define W_F4   (D_DIM * D_DIM / 4)          // 262144 per matrix
#define CVT_F4 (X_F4 + 3 * W_F4)            // 4980736

__global__ void convert_kernel(const float* __restrict__ x,
                               const float* __restrict__ Wg,
                               const float* __restrict__ Wv,
                               const float* __restrict__ Wd) {
    // reset chained-scan state for this launch (stream-ordered before GEMM)
    if (blockIdx.x == 0) {
        if (threadIdx.x == 0) g_ticket = 0;
        for (int i = threadIdx.x; i < 64 * 16; i += 256) g_flags[i] = 0u;
    }

    int gid = blockIdx.x * blockDim.x + threadIdx.x;
    const float* src;
    uint2* dst;
    int r;
    if (gid < X_F4) {
        src = x; dst = (uint2*)g_xh; r = gid;
    } else {
        int t = gid - X_F4;
        int which = t / W_F4;
        r = t - which * W_F4;
        src = (which == 0) ? Wg : (which == 1) ? Wv : Wd;
        dst = (uint2*)g_w[which];
    }
    float4 v = ((const float4*)src)[r];
    union { __half h[4]; uint2 u; } hv;
    hv.h[0] = __float2half_rn(v.x);
    hv.h[1] = __float2half_rn(v.y);
    hv.h[2] = __float2half_rn(v.z);
    hv.h[3] = __float2half_rn(v.w);
    dst[r] = hv.u;
}

// ============================================================================
// Kernel 2: fully fused  triple GEMM + gates + single-pass chained scan + out
//   1024 CTAs, atomic-ticket vid -> (chain = vid/16, mpos = vid%16)
//   chain = (batch, nblk); CTA tile = 256 time steps x 64 channels.
//   Mainloop: fp16 mma.sync, 3-stage cp.async pipeline (as R8-R11).
//   Epilogue: gates (fp32, unquantized) -> smem; two-level in-smem scan;
//   inter-CTA h-carry via acquire/release flag chain; direct out stores.
// ============================================================================
#define BK 64
#define KCHUNKS 16
#define NSTAGE 3
#define TSTRIDE_B 144                       // 64 fp16 + 8 pad, in bytes
#define XT_BYTES (256 * TSTRIDE_B)          // 36864
#define WT_BYTES (64 * TSTRIDE_B)           // 9216
#define STAGE_BYTES (XT_BYTES + 3 * WT_BYTES)       // 64512
#define GEMM_SMEM (NSTAGE * STAGE_BYTES)            // 193536

__device__ __forceinline__ void stage_load(uint32_t sbase, int m0, int n0,
                                           int k0, int tid) {
    #pragma unroll
    for (int it = 0; it < 4; it++) {
        int idx = tid + it * 512;            // 0..2047
        int row = idx >> 3, c16 = idx & 7;
        cp16(sbase + row * TSTRIDE_B + c16 * 16,
             g_xh + (size_t)(m0 + row) * 1024 + k0 + c16 * 8);
    }
    #pragma unroll
    for (int w = 0; w < 3; w++) {
        int row = tid >> 3, c16 = tid & 7;
        cp16(sbase + XT_BYTES + w * WT_BYTES + row * TSTRIDE_B + c16 * 16,
             g_w[w] + (size_t)(n0 + row) * 1024 + k0 + c16 * 8);
    }
}

__global__ __launch_bounds__(512, 1)
void gemm3_kernel(const float* __restrict__ bgp,
                  const float* __restrict__ bvp,
                  const float* __restrict__ bdp,
                  float* __restrict__ out) {
    extern __shared__ char smem[];
    const uint32_t smem_u = smem_to_u32(smem);
    const int tid  = threadIdx.x;
    const int wid  = tid >> 5;
    const int lane = tid & 31;
    const int gid  = lane >> 2;            // 0..7
    const int tig  = lane & 3;             // 0..3
    const int warp_m = wid >> 1;           // 0..7
    const int warp_n = wid & 1;            // 0..1

    // ---- atomic-ticket virtual block id (chain-safe scheduling order)
    __shared__ int s_vid;
    if (tid == 0) s_vid = atomicAdd(&g_ticket, 1);
    __syncthreads();
    const int vid     = s_vid;
    const int mpos    = vid & 15;          // position along the time chain
    const int chainid = vid >> 4;          // 0..63 = (batch, nblk)
    const int m0 = (chainid & 3) * 4096 + mpos * 256;
    const int n0 = (chainid >> 2) * 64;

    // ldmatrix lane-address components
    const int l8   = lane & 7;
    const int q    = lane >> 3;
    const int a_row_off = l8 + (q & 1) * 8;
    const int a_k_off   = (q >> 1) * 16;   // bytes
    const int b_row_off = l8 + (q >> 1) * 8;
    const int b_k_off   = (q & 1) * 16;    // bytes

    float acc[3][2][4][4];                 // [out][mt][nt][frag] = 96 regs
    #pragma unroll
    for (int w = 0; w < 3; w++)
        #pragma unroll
        for (int mt = 0; mt < 2; mt++)
            #pragma unroll
            for (int nt = 0; nt < 4; nt++)
                #pragma unroll
                for (int f = 0; f < 4; f++) acc[w][mt][nt][f] = 0.f;

    // prologue: fill stages 0 and 1
    stage_load(smem_u,               m0, n0, 0,  tid); cp_commit();
    stage_load(smem_u + STAGE_BYTES, m0, n0, BK, tid); cp_commit();

    int sidx = 0;
    for (int ch = 0; ch < KCHUNKS; ch++) {
        if (ch + 1 < KCHUNKS)
            asm volatile("cp.async.wait_group 1;" ::: "memory");
        else
            asm volatile("cp.async.wait_group 0;" ::: "memory");
        __syncthreads();

        if (ch + 2 < KCHUNKS) {
            int pidx = sidx + 2 >= NSTAGE ? sidx + 2 - NSTAGE : sidx + 2;
            stage_load(smem_u + pidx * STAGE_BYTES, m0, n0, (ch + 2) * BK, tid);
            cp_commit();
        }

        const uint32_t sb = smem_u + sidx * STAGE_BYTES;
        #pragma unroll
        for (int ks = 0; ks < 4; ks++) {
            uint32_t ah[2][4];
            #pragma unroll
            for (int mt = 0; mt < 2; mt++) {
                uint32_t addr = sb
                    + (warp_m * 32 + mt * 16 + a_row_off) * TSTRIDE_B
                    + ks * 32 + a_k_off;
                ldsm4(ah[mt], addr);
            }
            #pragma unroll
            for (int w = 0; w < 3; w++) {
                const uint32_t wb = sb + XT_BYTES + w * WT_BYTES;
                uint32_t bfr[4][2];
                #pragma unroll
                for (int p = 0; p < 2; p++) {
                    uint32_t addr = wb
                        + (warp_n * 32 + p * 16 + b_row_off) * TSTRIDE_B
                        + ks * 32 + b_k_off;
                    uint32_t r[4];
                    ldsm4(r, addr);
                    bfr[p * 2    ][0] = r[0]; bfr[p * 2    ][1] = r[1];
                    bfr[p * 2 + 1][0] = r[2]; bfr[p * 2 + 1][1] = r[3];
                }
                #pragma unroll
                for (int mt = 0; mt < 2; mt++)
                    #pragma unroll
                    for (int nt = 0; nt < 4; nt++)
                        mma16816(acc[w][mt][nt], ah[mt], bfr[nt]);
            }
        }
        sidx = sidx + 1 >= NSTAGE ? 0 : sidx + 1;
    }
    __syncthreads();   // all warps done with stage buffers before smem reuse

    // ---- epilogue smem layout (149760 B < GEMM_SMEM)
    float* sA    = (float*)smem;           // [256][65]
    float* sX    = sA + 256 * 65;          // [256][65]  (later: final h)
    float* sP    = sX + 256 * 65;          // [16][64] sub-chunk a-products
    float* sH    = sP + 1024;              // [16][64] sub-chunk local h-ends
    float* sSeed = sH + 1024;              // [16][64] exclusive X-prefix
    float* sPx   = sSeed + 1024;           // [16][64] exclusive A-prefix
    float* sHin  = sPx + 1024;             // [64] incoming carry

    // ---- gates -> smem (full fp32, no quantization)
    #pragma unroll
    for (int mt = 0; mt < 2; mt++) {
        #pragma unroll
        for (int half = 0; half < 2; half++) {
            const int mloc = warp_m * 32 + mt * 16 + gid + half * 8;
            #pragma unroll
            for (int nt = 0; nt < 4; nt++) {
                const int nl = warp_n * 32 + nt * 8 + tig * 2;
                const int n = n0 + nl;
                #pragma unroll
                for (int j = 0; j < 2; j++) {
                    const int f = half * 2 + j;
                    float gg = acc[0][mt][nt][f] + __ldg(bgp + n + j);
                    float vv = acc[1][mt][nt][f] + __ldg(bvp + n + j);
                    float dd = acc[2][mt][nt][f] + __ldg(bdp + n + j);
                    float sg = 1.f / (1.f + __expf(-gg));
                    float sd = 1.f / (1.f + __expf(-dd));
                    sA[mloc * 65 + nl + j] = 0.001f + 0.998f * sd;
                    sX[mloc * 65 + nl + j] = sg * tanhf(vv);
                }
            }
        }
    }
    __syncthreads();

    // ---- step 1: sub-chunk local scans (16 subs x 64 ch, 2 units/thread)
    #pragma unroll
    for (int it = 0; it < 2; it++) {
        const int idx = tid + it * 512;
        const int sub = idx >> 6, nl = idx & 63;
        float h = 0.f, p = 1.f;
        #pragma unroll
        for (int i = 0; i < 16; i++) {
            const int mloc = sub * 16 + i;
            h = fmaf(sA[mloc * 65 + nl], h, sX[mloc * 65 + nl]);
            p *= sA[mloc * 65 + nl];
        }
        sP[sub * 64 + nl] = p;
        sH[sub * 64 + nl] = h;
    }
    __syncthreads();

    // ---- steps 2+3: tile aggregate, inter-CTA carry chain (threads 0..63)
    if (tid < 64) {
        float A = 1.f, X = 0.f;
        #pragma unroll
        for (int s = 0; s < 16; s++) {
            sSeed[s * 64 + tid] = X;
            sPx  [s * 64 + tid] = A;
            X = fmaf(sP[s * 64 + tid], X, sH[s * 64 + tid]);
            A *= sP[s * 64 + tid];
        }
        float hin = 0.f;
        if (mpos > 0) {
            const int pidx = chainid * 16 + mpos - 1;
            unsigned f;
            do {
                asm volatile("ld.acquire.gpu.b32 %0, [%1];"
                             : "=r"(f) : "l"(g_flags + pidx) : "memory");
            } while (f == 0u);
            hin = g_carry[pidx * 64 + tid];
        }
        sHin[tid] = hin;
        g_carry[(chainid * 16 + mpos) * 64 + tid] = fmaf(A, hin, X);
    }
    __syncthreads();   // carry data stores + sHin visible
    if (tid == 0) {
        __threadfence();
        asm volatile("st.release.gpu.b32 [%0], %1;"
                     :: "l"(g_flags + chainid * 16 + mpos), "r"(1u) : "memory");
    }

    // ---- steps 4+5: seeded re-scan, final h overwrites sX
    #pragma unroll
    for (int it = 0; it < 2; it++) {
        const int idx = tid + it * 512;
        const int sub = idx >> 6, nl = idx & 63;
        float h = fmaf(sPx[sub * 64 + nl], sHin[nl], sSeed[sub * 64 + nl]);
        #pragma unroll
        for (int i = 0; i < 16; i++) {
            const int mloc = sub * 16 + i;
            h = fmaf(sA[mloc * 65 + nl], h, sX[mloc * 65 + nl]);
            sX[mloc * 65 + nl] = h;
        }
    }
    __syncthreads();

    // ---- step 6: tile store (256 rows x 64 ch, float4)
    #pragma unroll
    for (int k2 = 0; k2 < 8; k2++) {
        const int fidx = tid + k2 * 512;    // 0..4095
        const int row = fidx >> 4, c4 = fidx & 15;
        float4 v;
        v.x = sX[row * 65 + c4 * 4 + 0];
        v.y = sX[row * 65 + c4 * 4 + 1];
        v.z = sX[row * 65 + c4 * 4 + 2];
        v.w = sX[row * 65 + c4 * 4 + 3];
        *(float4*)(out + (size_t)(m0 + row) * 1024 + n0 + c4 * 4) = v;
    }
}

// ============================================================================
// Launch
// ============================================================================
extern "C" void kernel_launch(void* const* d_in, const int* in_sizes, int n_in,
                              void* d_out, int out_size) {
    const float* x  = (const float*)d_in[0];
    const float* Wg = (const float*)d_in[1];
    const float* bg = (const float*)d_in[2];
    const float* Wv = (const float*)d_in[3];
    const float* bv = (const float*)d_in[4];
    const float* Wd = (const float*)d_in[5];
    const float* bd = (const float*)d_in[6];
    float* out = (float*)d_out;
    (void)in_sizes; (void)n_in; (void)out_size;

    convert_kernel<<<CVT_F4 / 256, 256>>>(x, Wg, Wv, Wd);

    cudaFuncSetAttribute(gemm3_kernel,
                         cudaFuncAttributeMaxDynamicSharedMemorySize, GEMM_SMEM);
    gemm3_kernel<<<1024, 512, GEMM_SMEM>>>(bg, bv, bd, out);
}

// round 14
// speedup vs baseline: 1.1270x; 1.1270x over previous
#include <cuda_runtime.h>
#include <cuda_fp16.h>
#include <cstdint>

// ============================================================================
// Problem dims
// ============================================================================
#define B_DIM 4
#define S_DIM 4096
#define D_DIM 1024
#define M_TOT (B_DIM * S_DIM)   // 16384

// ============================================================================
// Device scratch (allocation-free rule -> static __device__ arrays)
// ============================================================================
__device__ __align__(128) __half g_xh[M_TOT * D_DIM];     // 32 MB (x as fp16)
__device__ __align__(128) __half g_w[3][D_DIM * D_DIM];   // 6 MB  (Wg,Wv,Wd fp16)
// chained-scan state: 64 chains x 16 positions x 64 channels
__device__ __align__(128) float        g_pA   [64 * 16 * 64];  // partial A
__device__ __align__(128) float        g_pX   [64 * 16 * 64];  // partial X
__device__ __align__(128) float        g_carry[64 * 16 * 64];  // inclusive h
__device__ __align__(128) unsigned int g_flags[64 * 16];       // 0/1=partial/2=inclusive
__device__ int g_ticket;

// ============================================================================
// PTX helpers (sm_80-level features: mma.sync + cp.async + ldmatrix)
// ============================================================================
__device__ __forceinline__ uint32_t smem_to_u32(const void* p) {
    uint32_t a;
    asm("{ .reg .u64 t; cvta.to.shared.u64 t, %1; cvt.u32.u64 %0, t; }"
        : "=r"(a) : "l"(p));
    return a;
}

__device__ __forceinline__ void cp16(uint32_t dst, const void* src) {
    asm volatile("cp.async.cg.shared.global [%0], [%1], 16;"
                 :: "r"(dst), "l"(src) : "memory");
}
__device__ __forceinline__ void cp_commit() {
    asm volatile("cp.async.commit_group;" ::: "memory");
}

__device__ __forceinline__ void ldsm4(uint32_t* r, uint32_t addr) {
    asm volatile("ldmatrix.sync.aligned.m8n8.x4.shared.b16 {%0,%1,%2,%3}, [%4];"
                 : "=r"(r[0]), "=r"(r[1]), "=r"(r[2]), "=r"(r[3]) : "r"(addr));
}

// D += A * B  (m16n8k16, fp16 in, f32 accum, A row-major, B col-major)
__device__ __forceinline__ void mma16816(float* c, const uint32_t* a, const uint32_t* b) {
    asm volatile(
        "mma.sync.aligned.m16n8k16.row.col.f32.f16.f16.f32 "
        "{%0,%1,%2,%3}, {%4,%5,%6,%7}, {%8,%9}, {%0,%1,%2,%3};"
        : "+f"(c[0]), "+f"(c[1]), "+f"(c[2]), "+f"(c[3])
        : "r"(a[0]), "r"(a[1]), "r"(a[2]), "r"(a[3]), "r"(b[0]), "r"(b[1]));
}

// ============================================================================
// Kernel 1: fused fp32 -> fp16 conversion + per-launch sync-state reset
// ============================================================================
#define X_F4   (M_TOT * D_DIM / 4)          // 4194304 float4s
#define W_F4   (D_DIM * D_DIM / 4)          // 262144 per matrix
#define CVT_F4 (X_F4 + 3 * W_F4)            // 4980736

__global__ void convert_kernel(const float* __restrict__ x,
                               const float* __restrict__ Wg,
                               const float* __restrict__ Wv,
                               const float* __restrict__ Wd) {
    // reset chained-scan state for this launch (stream-ordered before GEMM)
    if (blockIdx.x == 0) {
        if (threadIdx.x == 0) g_ticket = 0;
        for (int i = threadIdx.x; i < 64 * 16; i += 256) g_flags[i] = 0u;
    }

    int gid = blockIdx.x * blockDim.x + threadIdx.x;
    const float* src;
    uint2* dst;
    int r;
    if (gid < X_F4) {
        src = x; dst = (uint2*)g_xh; r = gid;
    } else {
        int t = gid - X_F4;
        int which = t / W_F4;
        r = t - which * W_F4;
        src = (which == 0) ? Wg : (which == 1) ? Wv : Wd;
        dst = (uint2*)g_w[which];
    }
    float4 v = ((const float4*)src)[r];
    union { __half h[4]; uint2 u; } hv;
    hv.h[0] = __float2half_rn(v.x);
    hv.h[1] = __float2half_rn(v.y);
    hv.h[2] = __float2half_rn(v.z);
    hv.h[3] = __float2half_rn(v.w);
    dst[r] = hv.u;
}

// ============================================================================
// Kernel 2: fused triple GEMM + gates + single-pass chained scan + out
//   1024 CTAs, atomic-ticket vid, mpos-MAJOR: mpos = vid/64, chain = vid%64
//   (predecessor holds a ticket 64 lower -> ~one wave earlier -> no stall).
//   Decoupled look-back: publish partial (A,X) flag=1 BEFORE waiting, then
//   inclusive carry flag=2; successors combine partials walking back.
// ============================================================================
#define BK 64
#define KCHUNKS 16
#define NSTAGE 3
#define TSTRIDE_B 144                       // 64 fp16 + 8 pad, in bytes
#define XT_BYTES (256 * TSTRIDE_B)          // 36864
#define WT_BYTES (64 * TSTRIDE_B)           // 9216
#define STAGE_BYTES (XT_BYTES + 3 * WT_BYTES)       // 64512
#define GEMM_SMEM (NSTAGE * STAGE_BYTES)            // 193536

__device__ __forceinline__ void stage_load(uint32_t sbase, int m0, int n0,
                                           int k0, int tid) {
    #pragma unroll
    for (int it = 0; it < 4; it++) {
        int idx = tid + it * 512;            // 0..2047
        int row = idx >> 3, c16 = idx & 7;
        cp16(sbase + row * TSTRIDE_B + c16 * 16,
             g_xh + (size_t)(m0 + row) * 1024 + k0 + c16 * 8);
    }
    #pragma unroll
    for (int w = 0; w < 3; w++) {
        int row = tid >> 3, c16 = tid & 7;
        cp16(sbase + XT_BYTES + w * WT_BYTES + row * TSTRIDE_B + c16 * 16,
             g_w[w] + (size_t)(n0 + row) * 1024 + k0 + c16 * 8);
    }
}

__global__ __launch_bounds__(512, 1)
void gemm3_kernel(const float* __restrict__ bgp,
                  const float* __restrict__ bvp,
                  const float* __restrict__ bdp,
                  float* __restrict__ out) {
    extern __shared__ char smem[];
    const uint32_t smem_u = smem_to_u32(smem);
    const int tid  = threadIdx.x;
    const int wid  = tid >> 5;
    const int lane = tid & 31;
    const int gid  = lane >> 2;            // 0..7
    const int tig  = lane & 3;             // 0..3
    const int warp_m = wid >> 1;           // 0..7
    const int warp_n = wid & 1;            // 0..1

    // ---- atomic-ticket virtual block id, mpos-MAJOR mapping
    __shared__ int s_vid;
    if (tid == 0) s_vid = atomicAdd(&g_ticket, 1);
    __syncthreads();
    const int vid     = s_vid;
    const int mpos    = vid >> 6;          // 0..15 position along time chain
    const int chainid = vid & 63;          // (batch, nblk)
    const int m0 = (chainid & 3) * 4096 + mpos * 256;
    const int n0 = (chainid >> 2) * 64;
    const int fidx0 = chainid * 16 + mpos; // this CTA's flag/carry index

    // ldmatrix lane-address components
    const int l8   = lane & 7;
    const int q    = lane >> 3;
    const int a_row_off = l8 + (q & 1) * 8;
    const int a_k_off   = (q >> 1) * 16;   // bytes
    const int b_row_off = l8 + (q >> 1) * 8;
    const int b_k_off   = (q & 1) * 16;    // bytes

    float acc[3][2][4][4];                 // [out][mt][nt][frag] = 96 regs
    #pragma unroll
    for (int w = 0; w < 3; w++)
        #pragma unroll
        for (int mt = 0; mt < 2; mt++)
            #pragma unroll
            for (int nt = 0; nt < 4; nt++)
                #pragma unroll
                for (int f = 0; f < 4; f++) acc[w][mt][nt][f] = 0.f;

    // prologue: fill stages 0 and 1
    stage_load(smem_u,               m0, n0, 0,  tid); cp_commit();
    stage_load(smem_u + STAGE_BYTES, m0, n0, BK, tid); cp_commit();

    int sidx = 0;
    for (int ch = 0; ch < KCHUNKS; ch++) {
        if (ch + 1 < KCHUNKS)
            asm volatile("cp.async.wait_group 1;" ::: "memory");
        else
            asm volatile("cp.async.wait_group 0;" ::: "memory");
        __syncthreads();

        if (ch + 2 < KCHUNKS) {
            int pidx = sidx + 2 >= NSTAGE ? sidx + 2 - NSTAGE : sidx + 2;
            stage_load(smem_u + pidx * STAGE_BYTES, m0, n0, (ch + 2) * BK, tid);
            cp_commit();
        }

        const uint32_t sb = smem_u + sidx * STAGE_BYTES;
        #pragma unroll
        for (int ks = 0; ks < 4; ks++) {
            uint32_t ah[2][4];
            #pragma unroll
            for (int mt = 0; mt < 2; mt++) {
                uint32_t addr = sb
                    + (warp_m * 32 + mt * 16 + a_row_off) * TSTRIDE_B
                    + ks * 32 + a_k_off;
                ldsm4(ah[mt], addr);
            }
            #pragma unroll
            for (int w = 0; w < 3; w++) {
                const uint32_t wb = sb + XT_BYTES + w * WT_BYTES;
                uint32_t bfr[4][2];
                #pragma unroll
                for (int p = 0; p < 2; p++) {
                    uint32_t addr = wb
                        + (warp_n * 32 + p * 16 + b_row_off) * TSTRIDE_B
                        + ks * 32 + b_k_off;
                    uint32_t r[4];
                    ldsm4(r, addr);
                    bfr[p * 2    ][0] = r[0]; bfr[p * 2    ][1] = r[1];
                    bfr[p * 2 + 1][0] = r[2]; bfr[p * 2 + 1][1] = r[3];
                }
                #pragma unroll
                for (int mt = 0; mt < 2; mt++)
                    #pragma unroll
                    for (int nt = 0; nt < 4; nt++)
                        mma16816(acc[w][mt][nt], ah[mt], bfr[nt]);
            }
        }
        sidx = sidx + 1 >= NSTAGE ? 0 : sidx + 1;
    }
    __syncthreads();   // all warps done with stage buffers before smem reuse

    // ---- epilogue smem layout (149760 B < GEMM_SMEM)
    float* sA    = (float*)smem;           // [256][65]
    float* sX    = sA + 256 * 65;          // [256][65]  (later: final h)
    float* sP    = sX + 256 * 65;          // [16][64] sub-chunk a-products
    float* sH    = sP + 1024;              // [16][64] sub-chunk local h-ends
    float* sSeed = sH + 1024;              // [16][64] exclusive X-prefix
    float* sPx   = sSeed + 1024;           // [16][64] exclusive A-prefix
    float* sHin  = sPx + 1024;             // [64] incoming carry

    // ---- gates -> smem (full fp32)
    #pragma unroll
    for (int mt = 0; mt < 2; mt++) {
        #pragma unroll
        for (int half = 0; half < 2; half++) {
            const int mloc = warp_m * 32 + mt * 16 + gid + half * 8;
            #pragma unroll
            for (int nt = 0; nt < 4; nt++) {
                const int nl = warp_n * 32 + nt * 8 + tig * 2;
                const int n = n0 + nl;
                #pragma unroll
                for (int j = 0; j < 2; j++) {
                    const int f = half * 2 + j;
                    float gg = acc[0][mt][nt][f] + __ldg(bgp + n + j);
                    float vv = acc[1][mt][nt][f] + __ldg(bvp + n + j);
                    float dd = acc[2][mt][nt][f] + __ldg(bdp + n + j);
                    float sg = 1.f / (1.f + __expf(-gg));
                    float sd = 1.f / (1.f + __expf(-dd));
                    sA[mloc * 65 + nl + j] = 0.001f + 0.998f * sd;
                    sX[mloc * 65 + nl + j] = sg * tanhf(vv);
                }
            }
        }
    }
    __syncthreads();

    // ---- step 1: sub-chunk local scans (16 subs x 64 ch, 2 units/thread)
    #pragma unroll
    for (int it = 0; it < 2; it++) {
        const int idx = tid + it * 512;
        const int sub = idx >> 6, nl = idx & 63;
        float h = 0.f, p = 1.f;
        #pragma unroll
        for (int i = 0; i < 16; i++) {
            const int mloc = sub * 16 + i;
            h = fmaf(sA[mloc * 65 + nl], h, sX[mloc * 65 + nl]);
            p *= sA[mloc * 65 + nl];
        }
        sP[sub * 64 + nl] = p;
        sH[sub * 64 + nl] = h;
    }
    __syncthreads();

    // ---- step 2: tile aggregate + PUBLISH PARTIAL (before any waiting)
    float aggA = 1.f, aggX = 0.f;
    if (tid < 64) {
        #pragma unroll
        for (int s = 0; s < 16; s++) {
            sSeed[s * 64 + tid] = aggX;
            sPx  [s * 64 + tid] = aggA;
            aggX = fmaf(sP[s * 64 + tid], aggX, sH[s * 64 + tid]);
            aggA *= sP[s * 64 + tid];
        }
        if (mpos > 0 && mpos < 15) {
            g_pA[fidx0 * 64 + tid] = aggA;
            g_pX[fidx0 * 64 + tid] = aggX;
        }
    }
    __syncthreads();
    if (tid == 0 && mpos > 0 && mpos < 15) {
        __threadfence();
        asm volatile("st.release.gpu.b32 [%0], %1;"
                     :: "l"(g_flags + fidx0), "r"(1u) : "memory");
    }

    // ---- step 3: decoupled look-back for the incoming carry
    if (tid < 64) {
        float hin = 0.f;
        if (mpos > 0) {
            float Ar = 1.f, Xr = 0.f;
            int j = mpos - 1;
            while (true) {
                const int pj = chainid * 16 + j;
                unsigned f;
                while (true) {
                    asm volatile("ld.acquire.gpu.b32 %0, [%1];"
                                 : "=r"(f) : "l"(g_flags + pj) : "memory");
                    if (f != 0u) break;
                    __nanosleep(60);
                }
                if (f == 2u) {                       // inclusive available
                    hin = fmaf(Ar, g_carry[pj * 64 + tid], Xr);
                    break;
                }
                // partial: fold and walk back (pos 0 always publishes 2)
                float Aj = g_pA[pj * 64 + tid];
                float Xj = g_pX[pj * 64 + tid];
                Xr = fmaf(Ar, Xj, Xr);
                Ar = Ar * Aj;
                j--;
            }
        }
        sHin[tid] = hin;
        if (mpos < 15)
            g_carry[fidx0 * 64 + tid] = fmaf(aggA, hin, aggX);
    }
    __syncthreads();   // inclusive stores + sHin visible
    if (tid == 0 && mpos < 15) {
        __threadfence();
        asm volatile("st.release.gpu.b32 [%0], %1;"
                     :: "l"(g_flags + fidx0), "r"(2u) : "memory");
    }

    // ---- steps 4+5: seeded re-scan, final h overwrites sX
    #pragma unroll
    for (int it = 0; it < 2; it++) {
        const int idx = tid + it * 512;
        const int sub = idx >> 6, nl = idx & 63;
        float h = fmaf(sPx[sub * 64 + nl], sHin[nl], sSeed[sub * 64 + nl]);
        #pragma unroll
        for (int i = 0; i < 16; i++) {
            const int mloc = sub * 16 + i;
            h = fmaf(sA[mloc * 65 + nl], h, sX[mloc * 65 + nl]);
            sX[mloc * 65 + nl] = h;
        }
    }
    __syncthreads();

    // ---- step 6: tile store (256 rows x 64 ch, float4)
    #pragma unroll
    for (int k2 = 0; k2 < 8; k2++) {
        const int fidx = tid + k2 * 512;    // 0..4095
        const int row = fidx >> 4, c4 = fidx & 15;
        float4 v;
        v.x = sX[row * 65 + c4 * 4 + 0];
        v.y = sX[row * 65 + c4 * 4 + 1];
        v.z = sX[row * 65 + c4 * 4 + 2];
        v.w = sX[row * 65 + c4 * 4 + 3];
        *(float4*)(out + (size_t)(m0 + row) * 1024 + n0 + c4 * 4) = v;
    }
}

// ============================================================================
// Launch
// ============================================================================
extern "C" void kernel_launch(void* const* d_in, const int* in_sizes, int n_in,
                              void* d_out, int out_size) {
    const float* x  = (const float*)d_in[0];
    const float* Wg = (const float*)d_in[1];
    const float* bg = (const float*)d_in[2];
    const float* Wv = (const float*)d_in[3];
    const float* bv = (const float*)d_in[4];
    const float* Wd = (const float*)d_in[5];
    const float* bd = (const float*)d_in[6];
    float* out = (float*)d_out;
    (void)in_sizes; (void)n_in; (void)out_size;

    convert_kernel<<<CVT_F4 / 256, 256>>>(x, Wg, Wv, Wd);

    cudaFuncSetAttribute(gemm3_kernel,
                         cudaFuncAttributeMaxDynamicSharedMemorySize, GEMM_SMEM);
    gemm3_kernel<<<1024, 512, GEMM_SMEM>>>(bg, bv, bd, out);
}